// round 14
// baseline (speedup 1.0000x reference)
#include <cuda_runtime.h>
#include <cuda_fp16.h>
#include <math.h>
#include <stdint.h>

// Problem constants
#define BB      4
#define TT      2048
#define HID     1024
#define NH      8
#define HD      128
#define KS      4
#define INTER   2816
#define MROWS   (BB * TT)            // 8192
#define NCHUNK  16
#define CLEN    128

// ---------------- scratch (float units) ------------------------------------
static const size_t SZ_MH = (size_t)MROWS * HID;      // 8388608
static const size_t SZ_MI = (size_t)MROWS * INTER;

static const size_t OFF_H     = 0;                            // half [M,HID]
static const size_t OFF_QKV   = OFF_H     + SZ_MH / 2;        // half [M,3H]
static const size_t OFF_CONV  = OFF_QKV   + 3 * SZ_MH / 2;    // half
static const size_t OFF_LOCAL = OFF_CONV  + SZ_MH / 2;        // half
static const size_t OFF_O     = OFF_LOCAL + SZ_MH / 2;        // half
static const size_t OFF_TMP   = OFF_O     + SZ_MH / 2;        // half
static const size_t OFF_O2    = OFF_TMP   + SZ_MH / 2;        // half
static const size_t OFF_ATTN  = OFF_O2    + SZ_MH / 2;        // half
static const size_t OFF_H2    = OFF_ATTN  + SZ_MH / 2;        // half
static const size_t OFF_FFA   = OFF_H2    + SZ_MH / 2;        // half [M,INTER]
static const size_t OFF_RKS   = OFF_FFA   + SZ_MI / 2;        // half [M,HID]
static const size_t OFF_RKV   = OFF_RKS   + SZ_MH / 2;        // half [M,HID]
static const size_t OFF_CKS   = OFF_RKV   + SZ_MH / 2;        // fp32 carries
static const size_t OFF_CKV   = OFF_CKS   + 65536;
static const size_t OFF_PKS   = OFF_CKV   + 65536;
static const size_t OFF_PKV   = OFF_PKS   + 65536;
// half weight copies
static const size_t OFF_WQKV  = OFF_PKV   + 65536;
static const size_t OFF_WOP   = OFF_WQKV  + 3 * (size_t)HID * HID / 2;
static const size_t OFF_WOG   = OFF_WOP   + (size_t)HID * HID / 2;
static const size_t OFF_WPW   = OFF_WOG   + (size_t)HID * HID / 2;
static const size_t OFF_WGT   = OFF_WPW   + (size_t)HID * HID / 2;
static const size_t OFF_WW3   = OFF_WGT   + (size_t)HID * HID;
static const size_t OFF_W12   = OFF_WW3   + (size_t)INTER * HID / 2;
static const size_t SCRATCH_FLOATS = OFF_W12 + (size_t)INTER * HID;

__device__ float g_scratch[SCRATCH_FLOATS];

// ---------------- helpers ----------------
__device__ __forceinline__ float sigmoidf_(float x) { return 1.0f / (1.0f + expf(-x)); }
__device__ __forceinline__ float siluf_(float x)    { return x / (1.0f + expf(-x)); }
__device__ __forceinline__ float elup1_(float x)    { return (x > 0.0f) ? (x + 1.0f) : expf(x); }

__device__ __forceinline__ uint2 f4_to_h4(float4 v) {
    __half2 a = __floats2half2_rn(v.x, v.y);
    __half2 b = __floats2half2_rn(v.z, v.w);
    uint2 r;
    r.x = *(unsigned*)&a;
    r.y = *(unsigned*)&b;
    return r;
}

__device__ __forceinline__ void mma_f16(float* c, const unsigned* a, const unsigned* b) {
    asm volatile("mma.sync.aligned.m16n8k16.row.col.f32.f16.f16.f32 "
        "{%0,%1,%2,%3}, {%4,%5,%6,%7}, {%8,%9}, {%0,%1,%2,%3};"
        : "+f"(c[0]), "+f"(c[1]), "+f"(c[2]), "+f"(c[3])
        : "r"(a[0]), "r"(a[1]), "r"(a[2]), "r"(a[3]), "r"(b[0]), "r"(b[1]));
}

__device__ __forceinline__ void ldsm_x4(unsigned* r, unsigned addr) {
    asm volatile("ldmatrix.sync.aligned.m8n8.x4.shared.b16 {%0,%1,%2,%3}, [%4];"
        : "=r"(r[0]), "=r"(r[1]), "=r"(r[2]), "=r"(r[3]) : "r"(addr));
}

// ---------------- fused weight prep: fp32 -> fp16, interleave w1/w2 --------
#define F4_QKV  786432u
#define F4_SQ   262144u
#define F4_GT   524288u
#define F4_W    720896u
#define C0 (F4_QKV)
#define C1 (C0 + F4_SQ)
#define C2 (C1 + F4_SQ)
#define C3 (C2 + F4_SQ)
#define C4 (C3 + F4_GT)
#define C5 (C4 + F4_W)
#define C6 (C5 + F4_W)
#define C7 (C6 + F4_W)

__global__ void weight_prep_kernel(const float4* __restrict__ qkv_w,
                                   const float4* __restrict__ op_w,
                                   const float4* __restrict__ og_w,
                                   const float4* __restrict__ pw_w,
                                   const float4* __restrict__ gt_w,
                                   const float4* __restrict__ w3,
                                   const float4* __restrict__ w1,
                                   const float4* __restrict__ w2,
                                   uint2* __restrict__ c_qkv,
                                   uint2* __restrict__ c_op,
                                   uint2* __restrict__ c_og,
                                   uint2* __restrict__ c_pw,
                                   uint2* __restrict__ c_gt,
                                   uint2* __restrict__ c_w3,
                                   uint2* __restrict__ c_w12) {
    unsigned i = blockIdx.x * blockDim.x + threadIdx.x;
    if (i < C0) {
        c_qkv[i] = f4_to_h4(qkv_w[i]);
    } else if (i < C1) {
        unsigned j = i - C0; c_op[j] = f4_to_h4(op_w[j]);
    } else if (i < C2) {
        unsigned j = i - C1; c_og[j] = f4_to_h4(og_w[j]);
    } else if (i < C3) {
        unsigned j = i - C2; c_pw[j] = f4_to_h4(pw_w[j]);
    } else if (i < C4) {
        unsigned j = i - C3; c_gt[j] = f4_to_h4(gt_w[j]);
    } else if (i < C5) {
        unsigned j = i - C4; c_w3[j] = f4_to_h4(w3[j]);
    } else if (i < C6) {
        unsigned j = i - C5;
        unsigned row = j >> 8, col = j & 255;
        c_w12[((size_t)(2 * row)) * 256 + col] = f4_to_h4(w1[j]);
    } else if (i < C7) {
        unsigned j = i - C6;
        unsigned row = j >> 8, col = j & 255;
        c_w12[((size_t)(2 * row + 1)) * 256 + col] = f4_to_h4(w2[j]);
    }
}

// ---------------- rmsnorm: fp32 in, half out -------------------------------
__global__ void rmsnorm_kernel(const float* __restrict__ x, const float* __restrict__ w,
                               __half* __restrict__ o) {
    int row = blockIdx.x;
    size_t base = (size_t)row * HID;
    float4 v = ((const float4*)(x + base))[threadIdx.x];
    float ss = v.x * v.x + v.y * v.y + v.z * v.z + v.w * v.w;
    __shared__ float sred[8];
    int lane = threadIdx.x & 31, wid = threadIdx.x >> 5;
    #pragma unroll
    for (int k = 16; k; k >>= 1) ss += __shfl_xor_sync(0xFFFFFFFFu, ss, k);
    if (lane == 0) sred[wid] = ss;
    __syncthreads();
    if (wid == 0) {
        float t = (lane < 8) ? sred[lane] : 0.0f;
        #pragma unroll
        for (int k = 4; k; k >>= 1) t += __shfl_xor_sync(0xFFFFFFFFu, t, k);
        if (lane == 0) sred[0] = t;
    }
    __syncthreads();
    float scale = rsqrtf(sred[0] * (1.0f / (float)HID) + 1e-6f);
    float4 wv = ((const float4*)w)[threadIdx.x];
    uint2 r = f4_to_h4(make_float4(v.x * scale * wv.x, v.y * scale * wv.y,
                                   v.z * scale * wv.z, v.w * scale * wv.w));
    ((uint2*)(o + base))[threadIdx.x] = r;
}

// ---------------- FP16 tensor-core GEMM (256x128 CTA tile) -----------------
// C = A[M,K] @ W[N,K]^T, half in, fp32 accum. CTA tile 256x128, K-tile 64,
// 512 threads / 16 warps (4x4), warp 64x32 via m16n8k16 + ldmatrix.x4.
// 3-stage cp.async, 1 CTA/SM (16 warps). u32 pitch 36, conflict-free.
// EPI: 0 store half, 1 accumulate fp32, 2 out-gate mix (half), 3 swiglu (half)
#define UPITCH  36
#define ABUF_U  (256 * UPITCH)               // A stage u32
#define BBUF_U  (128 * UPITCH)               // B stage u32
#define NSTG    3
#define TGEMM_SMEM ((ABUF_U + BBUF_U) * NSTG * 4)   // 165888 bytes

__device__ __forceinline__ void tile_load_a(unsigned* s, const __half* g, int ld,
                                            int k0, int tid) {
    #pragma unroll
    for (int i = 0; i < 4; i++) {
        int idx = tid + i * 512;             // 0..2047 (256 rows x 8 granules)
        int row = idx >> 3;
        int gr  = idx & 7;
        unsigned saddr = (unsigned)__cvta_generic_to_shared(s + row * UPITCH + gr * 4);
        const __half* gp = g + (size_t)row * ld + k0 + gr * 8;
        asm volatile("cp.async.cg.shared.global [%0], [%1], 16;" :: "r"(saddr), "l"(gp));
    }
}
__device__ __forceinline__ void tile_load_b(unsigned* s, const __half* g, int ld,
                                            int k0, int tid) {
    #pragma unroll
    for (int i = 0; i < 2; i++) {
        int idx = tid + i * 512;             // 0..1023 (128 rows x 8 granules)
        int row = idx >> 3;
        int gr  = idx & 7;
        unsigned saddr = (unsigned)__cvta_generic_to_shared(s + row * UPITCH + gr * 4);
        const __half* gp = g + (size_t)row * ld + k0 + gr * 8;
        asm volatile("cp.async.cg.shared.global [%0], [%1], 16;" :: "r"(saddr), "l"(gp));
    }
}

template <int EPI>
__global__ __launch_bounds__(512, 1)
void hgemm_kernel(const __half* __restrict__ A, const __half* __restrict__ A2,
                  int ksplit, int ldA,
                  const __half* __restrict__ W, int ldW,
                  void* __restrict__ Cv, int ldC, int K,
                  const float* __restrict__ gb,
                  const __half* __restrict__ oin,
                  const __half* __restrict__ qkvp) {
    extern __shared__ unsigned smem[];
    unsigned* AsB = smem;                          // 3 stages of A (256 rows)
    unsigned* WsB = smem + NSTG * ABUF_U;          // 3 stages of B (128 rows)
    int tid = threadIdx.x;
    int wid = tid >> 5, lane = tid & 31;
    int warp_m = wid & 3, warp_n = wid >> 2;       // 4 x 4 warp grid
    int m0 = blockIdx.y * 256, n0 = blockIdx.x * 128;
    const __half* Ag  = A  + (size_t)m0 * ldA;
    const __half* Ag2 = A2 + (size_t)m0 * ldA;
    const __half* Wg  = W  + (size_t)n0 * ldW;
    int qr = lane >> 2, qc = lane & 3;

    int mi = lane >> 3, rr = lane & 7;
    int lrow_a = warp_m * 64 + (mi & 1) * 8 + rr;
    int lrow_b = warp_n * 32 + (mi & 1) * 8 + rr;
    int lcol   = (mi >> 1) * 4;

    unsigned aBase = (unsigned)__cvta_generic_to_shared(AsB);
    unsigned bBase = (unsigned)__cvta_generic_to_shared(WsB);

    float acc[4][4][4];
    #pragma unroll
    for (int mt = 0; mt < 4; mt++)
        #pragma unroll
        for (int nt = 0; nt < 4; nt++)
            #pragma unroll
            for (int i = 0; i < 4; i++) acc[mt][nt][i] = 0.0f;

    int KT = K / 64;   // >= 16 for all our GEMMs

    #pragma unroll
    for (int p = 0; p < 2; p++) {
        int k0 = p * 64;
        const __half* a0 = (k0 < ksplit) ? Ag : Ag2;
        int ak0 = (k0 < ksplit) ? k0 : k0 - ksplit;
        tile_load_a(AsB + p * ABUF_U, a0, ldA, ak0, tid);
        tile_load_b(WsB + p * BBUF_U, Wg, ldW, k0, tid);
        asm volatile("cp.async.commit_group;" ::: "memory");
    }

    for (int kt = 0; kt < KT; kt++) {
        int cur = kt % NSTG;
        if (kt + 1 < KT) asm volatile("cp.async.wait_group 1;" ::: "memory");
        else             asm volatile("cp.async.wait_group 0;" ::: "memory");
        __syncthreads();
        if (kt + 2 < KT) {
            int k0 = (kt + 2) * 64;
            int slot = (kt + 2) % NSTG;
            const __half* a0 = (k0 < ksplit) ? Ag : Ag2;
            int ak0 = (k0 < ksplit) ? k0 : k0 - ksplit;
            tile_load_a(AsB + slot * ABUF_U, a0, ldA, ak0, tid);
            tile_load_b(WsB + slot * BBUF_U, Wg, ldW, k0, tid);
            asm volatile("cp.async.commit_group;" ::: "memory");
        }
        unsigned aT = aBase + (cur * ABUF_U + lrow_a * UPITCH + lcol) * 4;
        unsigned bT = bBase + (cur * BBUF_U + lrow_b * UPITCH + lcol) * 4;
        #pragma unroll
        for (int ks = 0; ks < 4; ks++) {
            unsigned af[4][4], bf[4][2];
            #pragma unroll
            for (int mt = 0; mt < 4; mt++)
                ldsm_x4(af[mt], aT + (mt * 16 * UPITCH + ks * 8) * 4);
            #pragma unroll
            for (int ntp = 0; ntp < 2; ntp++) {
                unsigned t[4];
                ldsm_x4(t, bT + (ntp * 16 * UPITCH + ks * 8) * 4);
                bf[2 * ntp][0] = t[0]; bf[2 * ntp + 1][0] = t[1];
                bf[2 * ntp][1] = t[2]; bf[2 * ntp + 1][1] = t[3];
            }
            #pragma unroll
            for (int mt = 0; mt < 4; mt++)
                #pragma unroll
                for (int nt = 0; nt < 4; nt++)
                    mma_f16(acc[mt][nt], af[mt], bf[nt]);
        }
    }

    #pragma unroll
    for (int mt = 0; mt < 4; mt++)
        #pragma unroll
        for (int nt = 0; nt < 4; nt++) {
            int row = m0 + warp_m * 64 + mt * 16 + qr;
            int col = n0 + warp_n * 32 + nt * 8 + qc * 2;
            float2 r0 = make_float2(acc[mt][nt][0], acc[mt][nt][1]);
            float2 r1 = make_float2(acc[mt][nt][2], acc[mt][nt][3]);
            if (EPI == 0) {
                __half* Ch = (__half*)Cv;
                *(__half2*)(Ch + (size_t)row * ldC + col)       = __floats2half2_rn(r0.x, r0.y);
                *(__half2*)(Ch + (size_t)(row + 8) * ldC + col) = __floats2half2_rn(r1.x, r1.y);
            } else if (EPI == 1) {
                float* Cf = (float*)Cv;
                float* p0 = Cf + (size_t)row * ldC + col;
                float* p1 = Cf + (size_t)(row + 8) * ldC + col;
                float2 o0 = *(float2*)p0, o1 = *(float2*)p1;
                *(float2*)p0 = make_float2(r0.x + o0.x, r0.y + o0.y);
                *(float2*)p1 = make_float2(r1.x + o1.x, r1.y + o1.y);
            } else if (EPI == 2) {
                __half* Ch = (__half*)Cv;
                float2 gbv = *(const float2*)(gb + col);
                float2 o0 = __half22float2(*(const __half2*)(oin + (size_t)row * HID + col));
                float2 o1 = __half22float2(*(const __half2*)(oin + (size_t)(row + 8) * HID + col));
                float2 v0 = __half22float2(*(const __half2*)(qkvp + (size_t)row * 3072 + 2048 + col));
                float2 v1 = __half22float2(*(const __half2*)(qkvp + (size_t)(row + 8) * 3072 + 2048 + col));
                float g00 = sigmoidf_(r0.x + gbv.x), g01 = sigmoidf_(r0.y + gbv.y);
                float g10 = sigmoidf_(r1.x + gbv.x), g11 = sigmoidf_(r1.y + gbv.y);
                *(__half2*)(Ch + (size_t)row * ldC + col) =
                    __floats2half2_rn(g00 * o0.x + (1.0f - g00) * v0.x,
                                      g01 * o0.y + (1.0f - g01) * v0.y);
                *(__half2*)(Ch + (size_t)(row + 8) * ldC + col) =
                    __floats2half2_rn(g10 * o1.x + (1.0f - g10) * v1.x,
                                      g11 * o1.y + (1.0f - g11) * v1.y);
            } else {  // EPI == 3
                __half* Ch = (__half*)Cv;
                int ocol = col >> 1;
                Ch[(size_t)row * ldC + ocol]       = __float2half_rn(siluf_(r0.x) * r0.y);
                Ch[(size_t)(row + 8) * ldC + ocol] = __float2half_rn(siluf_(r1.x) * r1.y);
            }
        }
}

// ---------------- depthwise conv (KS=4) + bias + silu ----------------------
__global__ void conv_silu_kernel(const __half* __restrict__ h, const float* __restrict__ cw,
                                 const float* __restrict__ cb, __half* __restrict__ o) {
    __shared__ float tapT[KS][HID];
    int tid = threadIdx.x;
    int row = blockIdx.x;
    int t = row & (TT - 1);
    int b = row >> 11;
    #pragma unroll
    for (int i = 0; i < 4; i++) {
        int ch = tid + i * 256;
        float4 w = *(const float4*)(cw + ch * KS);
        tapT[0][ch] = w.x; tapT[1][ch] = w.y; tapT[2][ch] = w.z; tapT[3][ch] = w.w;
    }
    __syncthreads();
    int c = tid * 4;
    float4 acc = *(const float4*)(cb + c);
    #pragma unroll
    for (int j = 0; j < KS; j++) {
        int tt = t + j - (KS - 1);
        if (tt >= 0) {
            uint2 hv4 = *(const uint2*)(h + ((size_t)(b * TT + tt)) * HID + c);
            float2 h01 = __half22float2(*(__half2*)&hv4.x);
            float2 h23 = __half22float2(*(__half2*)&hv4.y);
            float4 tp = *(const float4*)(&tapT[j][c]);
            acc.x += h01.x * tp.x; acc.y += h01.y * tp.y;
            acc.z += h23.x * tp.z; acc.w += h23.y * tp.w;
        }
    }
    uint2 r = f4_to_h4(make_float4(siluf_(acc.x), siluf_(acc.y),
                                   siluf_(acc.z), siluf_(acc.w)));
    *(uint2*)(o + (size_t)row * HID + c) = r;
}

// ---------------- scan pass A (elu+1 on k inline), half rks/rkv ------------
__global__ void scan_chunk_kernel(const __half* __restrict__ qkv, const float* __restrict__ dp,
                                  __half* __restrict__ rks, __half* __restrict__ rkv,
                                  float* __restrict__ cks, float* __restrict__ ckv) {
    int c = blockIdx.x * blockDim.x + threadIdx.x;
    int j = blockIdx.y;
    int b = blockIdx.z;
    float d = sigmoidf_(dp[c >> 7]);
    float sks = 0.0f, skv = 0.0f;
    size_t base  = ((size_t)(b * TT + j * CLEN)) * 3072 + c;
    size_t obase = ((size_t)(b * TT + j * CLEN)) * HID + c;
    for (int i = 0; i < CLEN; i++) {
        float kk = elup1_(__half2float(qkv[base + 1024]));
        float vv = __half2float(qkv[base + 2048]);
        sks = d * sks + kk;
        skv = d * skv + kk * vv;
        rks[obase] = __float2half_rn(sks);
        rkv[obase] = __float2half_rn(skv);
        base += 3072; obase += HID;
    }
    cks[(b * NCHUNK + j) * HID + c] = sks;
    ckv[(b * NCHUNK + j) * HID + c] = skv;
}

// ---------------- scan pass B ---------------------------------------------
__global__ void scan_carry_kernel(const float* __restrict__ dp,
                                  const float* __restrict__ cks, const float* __restrict__ ckv,
                                  float* __restrict__ pks, float* __restrict__ pkv) {
    int c = blockIdx.x * blockDim.x + threadIdx.x;
    int b = blockIdx.y;
    float d = sigmoidf_(dp[c >> 7]);
    float dC = expf((float)CLEN * logf(d));
    float sks = 0.0f, skv = 0.0f;
    for (int j = 0; j < NCHUNK; j++) {
        int idx = (b * NCHUNK + j) * HID + c;
        pks[idx] = sks;
        pkv[idx] = skv;
        sks = dC * sks + cks[idx];
        skv = dC * skv + ckv[idx];
    }
}

// ---------------- attn_o (fused elu/carry/den), half in/out ----------------
__global__ void attn_o_kernel(const __half* __restrict__ qkv, const float* __restrict__ dp,
                              const __half* __restrict__ rks, const __half* __restrict__ rkv,
                              const float* __restrict__ pks, const float* __restrict__ pkv,
                              __half* __restrict__ o) {
    int gw = (blockIdx.x * blockDim.x + threadIdx.x) >> 5;
    int lane = threadIdx.x & 31;
    int row = gw >> 3;
    int hh = gw & 7;
    int b = row >> 11;
    int t = row & (TT - 1);
    int i = t & (CLEN - 1);
    int j = t >> 7;
    float d  = sigmoidf_(dp[hh]);
    float pw = expf((float)(i + 1) * logf(d));
    size_t qbase = (size_t)row * 3072 + hh * HD;
    size_t rbase = (size_t)row * HID  + hh * HD;
    size_t pbase = (size_t)(b * NCHUNK + j) * HID + hh * HD;
    float qv[4], kvv[4], s = 0.0f;
    #pragma unroll
    for (int u = 0; u < 4; u++) {
        int dpos = lane + u * 32;
        qv[u] = elup1_(__half2float(qkv[qbase + dpos]));
        float ks = __half2float(rks[rbase + dpos]) + pks[pbase + dpos] * pw;
        kvv[u]  = __half2float(rkv[rbase + dpos]) + pkv[pbase + dpos] * pw;
        s += qv[u] * ks;
    }
    #pragma unroll
    for (int k = 16; k; k >>= 1) s += __shfl_xor_sync(0xFFFFFFFFu, s, k);
    float inv = 1.0f / fmaxf(s, 1e-6f);
    #pragma unroll
    for (int u = 0; u < 4; u++) {
        int dpos = lane + u * 32;
        o[rbase + dpos] = __float2half_rn(qv[u] * kvv[u] * inv);
    }
}

// ---------------- gmix residual + rmsnorm2 ---------------------------------
__global__ void gmix_norm_kernel(const float* __restrict__ x, const __half* __restrict__ glin,
                                 const __half* __restrict__ local, const __half* __restrict__ attn,
                                 const float* __restrict__ w2n,
                                 float* __restrict__ x1out, __half* __restrict__ h2) {
    int row = blockIdx.x;
    size_t base = (size_t)row * HID;
    int tid = threadIdx.x;
    float4 xv = ((const float4*)(x + base))[tid];
    uint2 gu = ((const uint2*)(glin + base))[tid];
    uint2 lu = ((const uint2*)(local + base))[tid];
    uint2 au = ((const uint2*)(attn + base))[tid];
    float2 g01 = __half22float2(*(__half2*)&gu.x), g23 = __half22float2(*(__half2*)&gu.y);
    float2 l01 = __half22float2(*(__half2*)&lu.x), l23 = __half22float2(*(__half2*)&lu.y);
    float2 a01 = __half22float2(*(__half2*)&au.x), a23 = __half22float2(*(__half2*)&au.y);
    float s0 = sigmoidf_(g01.x), s1 = sigmoidf_(g01.y);
    float s2 = sigmoidf_(g23.x), s3 = sigmoidf_(g23.y);
    float4 x1v = make_float4(xv.x + s0 * l01.x + (1.0f - s0) * a01.x,
                             xv.y + s1 * l01.y + (1.0f - s1) * a01.y,
                             xv.z + s2 * l23.x + (1.0f - s2) * a23.x,
                             xv.w + s3 * l23.y + (1.0f - s3) * a23.y);
    ((float4*)(x1out + base))[tid] = x1v;
    float ss = x1v.x * x1v.x + x1v.y * x1v.y + x1v.z * x1v.z + x1v.w * x1v.w;
    __shared__ float sred[8];
    int lane = tid & 31, wid = tid >> 5;
    #pragma unroll
    for (int k = 16; k; k >>= 1) ss += __shfl_xor_sync(0xFFFFFFFFu, ss, k);
    if (lane == 0) sred[wid] = ss;
    __syncthreads();
    if (wid == 0) {
        float t = (lane < 8) ? sred[lane] : 0.0f;
        #pragma unroll
        for (int k = 4; k; k >>= 1) t += __shfl_xor_sync(0xFFFFFFFFu, t, k);
        if (lane == 0) sred[0] = t;
    }
    __syncthreads();
    float scale = rsqrtf(sred[0] * (1.0f / (float)HID) + 1e-6f);
    float4 wv = ((const float4*)w2n)[tid];
    uint2 r = f4_to_h4(make_float4(x1v.x * scale * wv.x, x1v.y * scale * wv.y,
                                   x1v.z * scale * wv.z, x1v.w * scale * wv.w));
    ((uint2*)(h2 + base))[tid] = r;
}

// ---------------- host side ------------------------------------------------
#define BIGK 0x40000000

static inline void run_gemm(const __half* A, const __half* A2, int ksplit, int ldA,
                            const __half* W, int ldW,
                            void* C, int ldC, int M, int N, int K,
                            int epi,
                            const float* gb = nullptr, const __half* oin = nullptr,
                            const __half* qkvp = nullptr) {
    dim3 grid(N / 128, M / 256);
    if (epi == 3)
        hgemm_kernel<3><<<grid, 512, TGEMM_SMEM>>>(A, A2, ksplit, ldA, W, ldW, C, ldC, K, nullptr, nullptr, nullptr);
    else if (epi == 2)
        hgemm_kernel<2><<<grid, 512, TGEMM_SMEM>>>(A, A2, ksplit, ldA, W, ldW, C, ldC, K, gb, oin, qkvp);
    else if (epi == 1)
        hgemm_kernel<1><<<grid, 512, TGEMM_SMEM>>>(A, A2, ksplit, ldA, W, ldW, C, ldC, K, nullptr, nullptr, nullptr);
    else
        hgemm_kernel<0><<<grid, 512, TGEMM_SMEM>>>(A, A2, ksplit, ldA, W, ldW, C, ldC, K, nullptr, nullptr, nullptr);
}

extern "C" void kernel_launch(void* const* d_in, const int* in_sizes, int n_in,
                              void* d_out, int out_size) {
    const float* x           = (const float*)d_in[0];
    const float* qkv_w       = (const float*)d_in[1];
    const float* out_proj_w  = (const float*)d_in[2];
    const float* out_gate_w  = (const float*)d_in[3];
    const float* out_gate_b  = (const float*)d_in[4];
    const float* decay_param = (const float*)d_in[5];
    const float* conv_w      = (const float*)d_in[6];
    const float* conv_b      = (const float*)d_in[7];
    const float* pw_w        = (const float*)d_in[8];
    const float* gate_w      = (const float*)d_in[9];
    const float* w1          = (const float*)d_in[10];
    const float* w2          = (const float*)d_in[11];
    const float* w3          = (const float*)d_in[12];
    const float* norm1_w     = (const float*)d_in[13];
    const float* norm2_w     = (const float*)d_in[14];
    float* out = (float*)d_out;

    static int smem_set = 0;
    if (!smem_set) {
        cudaFuncSetAttribute(hgemm_kernel<0>,
                             cudaFuncAttributeMaxDynamicSharedMemorySize, (int)TGEMM_SMEM);
        cudaFuncSetAttribute(hgemm_kernel<1>,
                             cudaFuncAttributeMaxDynamicSharedMemorySize, (int)TGEMM_SMEM);
        cudaFuncSetAttribute(hgemm_kernel<2>,
                             cudaFuncAttributeMaxDynamicSharedMemorySize, (int)TGEMM_SMEM);
        cudaFuncSetAttribute(hgemm_kernel<3>,
                             cudaFuncAttributeMaxDynamicSharedMemorySize, (int)TGEMM_SMEM);
        smem_set = 1;
    }

    float* S = nullptr;
    cudaGetSymbolAddress((void**)&S, g_scratch);

    __half* g_h    = (__half*)(S + OFF_H);
    __half* g_qkv  = (__half*)(S + OFF_QKV);
    __half* g_conv = (__half*)(S + OFF_CONV);
    __half* g_loc  = (__half*)(S + OFF_LOCAL);
    __half* g_o    = (__half*)(S + OFF_O);
    __half* g_tmp  = (__half*)(S + OFF_TMP);
    __half* g_o2   = (__half*)(S + OFF_O2);
    __half* g_attn = (__half*)(S + OFF_ATTN);
    __half* g_h2   = (__half*)(S + OFF_H2);
    __half* g_ffa  = (__half*)(S + OFF_FFA);
    __half* g_rks  = (__half*)(S + OFF_RKS);
    __half* g_rkv  = (__half*)(S + OFF_RKV);
    float*  g_cks  = S + OFF_CKS;
    float*  g_ckv  = S + OFF_CKV;
    float*  g_pks  = S + OFF_PKS;
    float*  g_pkv  = S + OFF_PKV;
    __half* c_qkvw = (__half*)(S + OFF_WQKV);
    __half* c_opw  = (__half*)(S + OFF_WOP);
    __half* c_ogw  = (__half*)(S + OFF_WOG);
    __half* c_pww  = (__half*)(S + OFF_WPW);
    __half* c_gtw  = (__half*)(S + OFF_WGT);
    __half* c_w3   = (__half*)(S + OFF_WW3);
    __half* c_w12  = (__half*)(S + OFF_W12);

    // 0. one fused weight-prep launch
    weight_prep_kernel<<<(C7 + 255) / 256, 256>>>(
        (const float4*)qkv_w, (const float4*)out_proj_w, (const float4*)out_gate_w,
        (const float4*)pw_w, (const float4*)gate_w, (const float4*)w3,
        (const float4*)w1, (const float4*)w2,
        (uint2*)c_qkvw, (uint2*)c_opw, (uint2*)c_ogw, (uint2*)c_pww,
        (uint2*)c_gtw, (uint2*)c_w3, (uint2*)c_w12);

    // 1. h = rmsnorm(x, norm1_w)
    rmsnorm_kernel<<<MROWS, 256>>>(x, norm1_w, g_h);

    // 2. qkv = h @ qkv_w^T
    run_gemm(g_h, g_h, BIGK, HID, c_qkvw, HID, g_qkv, 3 * HID, MROWS, 3 * HID, HID, 0);

    // 3. conv branch
    conv_silu_kernel<<<MROWS, 256>>>(g_h, conv_w, conv_b, g_conv);
    run_gemm(g_conv, g_conv, BIGK, HID, c_pww, HID, g_loc, HID, MROWS, HID, HID, 0);

    // 4. decayed scans
    {
        dim3 gA(HID / 256, NCHUNK, BB);
        scan_chunk_kernel<<<gA, 256>>>(g_qkv, decay_param, g_rks, g_rkv, g_cks, g_ckv);
        dim3 gB(HID / 256, BB);
        scan_carry_kernel<<<gB, 256>>>(decay_param, g_cks, g_ckv, g_pks, g_pkv);
    }

    // 5. o
    attn_o_kernel<<<MROWS * NH * 32 / 256, 256>>>(g_qkv, decay_param,
                                                  g_rks, g_rkv, g_pks, g_pkv, g_o);

    // 6. out gate GEMM + fused mix epilogue -> o2
    run_gemm(g_o, g_o, BIGK, HID, c_ogw, HID, g_o2, HID, MROWS, HID, HID, 2,
             out_gate_b, g_o, g_qkv);

    // 7. attn = o2 @ out_proj^T
    run_gemm(g_o2, g_o2, BIGK, HID, c_opw, HID, g_attn, HID, MROWS, HID, HID, 0);

    // 8. gmix: dual-A GEMM over [local|attn] (K=2048), then residual+norm2
    run_gemm(g_loc, g_attn, HID, HID, c_gtw, 2 * HID, g_tmp, HID, MROWS, HID, 2 * HID, 0);
    gmix_norm_kernel<<<MROWS, 256>>>(x, g_tmp, g_loc, g_attn, norm2_w, out, g_h2);

    // 9. FFN: w1|w2 interleaved GEMM + swiglu epilogue -> ffa; w3 += onto out
    run_gemm(g_h2, g_h2, BIGK, HID, c_w12, HID, g_ffa, INTER, MROWS, 2 * INTER, HID, 3);
    run_gemm(g_ffa, g_ffa, BIGK, INTER, c_w3, INTER, out, HID, MROWS, HID, INTER, 1);
}

// round 15
// speedup vs baseline: 1.0864x; 1.0864x over previous
#include <cuda_runtime.h>
#include <cuda_fp16.h>
#include <math.h>
#include <stdint.h>

// Problem constants
#define BB      4
#define TT      2048
#define HID     1024
#define NH      8
#define HD      128
#define KS      4
#define INTER   2816
#define MROWS   (BB * TT)            // 8192
#define NCHUNK  16
#define CLEN    128

// ---------------- scratch (float units) ------------------------------------
static const size_t SZ_MH = (size_t)MROWS * HID;      // 8388608
static const size_t SZ_MI = (size_t)MROWS * INTER;

static const size_t OFF_H     = 0;                            // half [M,HID]
static const size_t OFF_QKV   = OFF_H     + SZ_MH / 2;        // half [M,3H]
static const size_t OFF_CONV  = OFF_QKV   + 3 * SZ_MH / 2;    // half
static const size_t OFF_LOCAL = OFF_CONV  + SZ_MH / 2;        // half
static const size_t OFF_O     = OFF_LOCAL + SZ_MH / 2;        // half
static const size_t OFF_TMP   = OFF_O     + SZ_MH / 2;        // half
static const size_t OFF_O2    = OFF_TMP   + SZ_MH / 2;        // half
static const size_t OFF_ATTN  = OFF_O2    + SZ_MH / 2;        // half
static const size_t OFF_H2    = OFF_ATTN  + SZ_MH / 2;        // half
static const size_t OFF_FFA   = OFF_H2    + SZ_MH / 2;        // half [M,INTER]
static const size_t OFF_RKS   = OFF_FFA   + SZ_MI / 2;        // half [M,HID]
static const size_t OFF_RKV   = OFF_RKS   + SZ_MH / 2;        // half [M,HID]
static const size_t OFF_CKS   = OFF_RKV   + SZ_MH / 2;        // fp32 carries
static const size_t OFF_CKV   = OFF_CKS   + 65536;
static const size_t OFF_PKS   = OFF_CKV   + 65536;
static const size_t OFF_PKV   = OFF_PKS   + 65536;
// half weight copies
static const size_t OFF_WQKV  = OFF_PKV   + 65536;
static const size_t OFF_WOP   = OFF_WQKV  + 3 * (size_t)HID * HID / 2;
static const size_t OFF_WOG   = OFF_WOP   + (size_t)HID * HID / 2;
static const size_t OFF_WPW   = OFF_WOG   + (size_t)HID * HID / 2;
static const size_t OFF_WGT   = OFF_WPW   + (size_t)HID * HID / 2;
static const size_t OFF_WW3   = OFF_WGT   + (size_t)HID * HID;
static const size_t OFF_W12   = OFF_WW3   + (size_t)INTER * HID / 2;
static const size_t SCRATCH_FLOATS = OFF_W12 + (size_t)INTER * HID;

__device__ float g_scratch[SCRATCH_FLOATS];

// ---------------- helpers ----------------
__device__ __forceinline__ float sigmoidf_(float x) { return 1.0f / (1.0f + expf(-x)); }
__device__ __forceinline__ float siluf_(float x)    { return x / (1.0f + expf(-x)); }
__device__ __forceinline__ float elup1_(float x)    { return (x > 0.0f) ? (x + 1.0f) : expf(x); }

__device__ __forceinline__ uint2 f4_to_h4(float4 v) {
    __half2 a = __floats2half2_rn(v.x, v.y);
    __half2 b = __floats2half2_rn(v.z, v.w);
    uint2 r;
    r.x = *(unsigned*)&a;
    r.y = *(unsigned*)&b;
    return r;
}

__device__ __forceinline__ void mma_f16(float* c, const unsigned* a, const unsigned* b) {
    asm volatile("mma.sync.aligned.m16n8k16.row.col.f32.f16.f16.f32 "
        "{%0,%1,%2,%3}, {%4,%5,%6,%7}, {%8,%9}, {%0,%1,%2,%3};"
        : "+f"(c[0]), "+f"(c[1]), "+f"(c[2]), "+f"(c[3])
        : "r"(a[0]), "r"(a[1]), "r"(a[2]), "r"(a[3]), "r"(b[0]), "r"(b[1]));
}

__device__ __forceinline__ void ldsm_x4(unsigned* r, unsigned addr) {
    asm volatile("ldmatrix.sync.aligned.m8n8.x4.shared.b16 {%0,%1,%2,%3}, [%4];"
        : "=r"(r[0]), "=r"(r[1]), "=r"(r[2]), "=r"(r[3]) : "r"(addr));
}

// ---------------- fused weight prep: fp32 -> fp16, interleave w1/w2 --------
#define F4_QKV  786432u
#define F4_SQ   262144u
#define F4_GT   524288u
#define F4_W    720896u
#define C0 (F4_QKV)
#define C1 (C0 + F4_SQ)
#define C2 (C1 + F4_SQ)
#define C3 (C2 + F4_SQ)
#define C4 (C3 + F4_GT)
#define C5 (C4 + F4_W)
#define C6 (C5 + F4_W)
#define C7 (C6 + F4_W)

__global__ void weight_prep_kernel(const float4* __restrict__ qkv_w,
                                   const float4* __restrict__ op_w,
                                   const float4* __restrict__ og_w,
                                   const float4* __restrict__ pw_w,
                                   const float4* __restrict__ gt_w,
                                   const float4* __restrict__ w3,
                                   const float4* __restrict__ w1,
                                   const float4* __restrict__ w2,
                                   uint2* __restrict__ c_qkv,
                                   uint2* __restrict__ c_op,
                                   uint2* __restrict__ c_og,
                                   uint2* __restrict__ c_pw,
                                   uint2* __restrict__ c_gt,
                                   uint2* __restrict__ c_w3,
                                   uint2* __restrict__ c_w12) {
    unsigned i = blockIdx.x * blockDim.x + threadIdx.x;
    if (i < C0) {
        c_qkv[i] = f4_to_h4(qkv_w[i]);
    } else if (i < C1) {
        unsigned j = i - C0; c_op[j] = f4_to_h4(op_w[j]);
    } else if (i < C2) {
        unsigned j = i - C1; c_og[j] = f4_to_h4(og_w[j]);
    } else if (i < C3) {
        unsigned j = i - C2; c_pw[j] = f4_to_h4(pw_w[j]);
    } else if (i < C4) {
        unsigned j = i - C3; c_gt[j] = f4_to_h4(gt_w[j]);
    } else if (i < C5) {
        unsigned j = i - C4; c_w3[j] = f4_to_h4(w3[j]);
    } else if (i < C6) {
        unsigned j = i - C5;
        unsigned row = j >> 8, col = j & 255;
        c_w12[((size_t)(2 * row)) * 256 + col] = f4_to_h4(w1[j]);
    } else if (i < C7) {
        unsigned j = i - C6;
        unsigned row = j >> 8, col = j & 255;
        c_w12[((size_t)(2 * row + 1)) * 256 + col] = f4_to_h4(w2[j]);
    }
}

// ---------------- rmsnorm: fp32 in, half out -------------------------------
__global__ void rmsnorm_kernel(const float* __restrict__ x, const float* __restrict__ w,
                               __half* __restrict__ o) {
    int row = blockIdx.x;
    size_t base = (size_t)row * HID;
    float4 v = ((const float4*)(x + base))[threadIdx.x];
    float ss = v.x * v.x + v.y * v.y + v.z * v.z + v.w * v.w;
    __shared__ float sred[8];
    int lane = threadIdx.x & 31, wid = threadIdx.x >> 5;
    #pragma unroll
    for (int k = 16; k; k >>= 1) ss += __shfl_xor_sync(0xFFFFFFFFu, ss, k);
    if (lane == 0) sred[wid] = ss;
    __syncthreads();
    if (wid == 0) {
        float t = (lane < 8) ? sred[lane] : 0.0f;
        #pragma unroll
        for (int k = 4; k; k >>= 1) t += __shfl_xor_sync(0xFFFFFFFFu, t, k);
        if (lane == 0) sred[0] = t;
    }
    __syncthreads();
    float scale = rsqrtf(sred[0] * (1.0f / (float)HID) + 1e-6f);
    float4 wv = ((const float4*)w)[threadIdx.x];
    uint2 r = f4_to_h4(make_float4(v.x * scale * wv.x, v.y * scale * wv.y,
                                   v.z * scale * wv.z, v.w * scale * wv.w));
    ((uint2*)(o + base))[threadIdx.x] = r;
}

// ---------------- FP16 tensor-core GEMM (R13 config: 128x128, 3-stage) -----
#define UPITCH 36
#define SBUF_U (128 * UPITCH)
#define NSTG   3
#define TGEMM_SMEM (2 * NSTG * SBUF_U * 4)    // 110592 bytes

__device__ __forceinline__ void tile_load_h(unsigned* s, const __half* g, int ld,
                                            int k0, int tid) {
    #pragma unroll
    for (int i = 0; i < 4; i++) {
        int idx = tid + i * 256;
        int row = idx >> 3;
        int gr  = idx & 7;
        unsigned saddr = (unsigned)__cvta_generic_to_shared(s + row * UPITCH + gr * 4);
        const __half* gp = g + (size_t)row * ld + k0 + gr * 8;
        asm volatile("cp.async.cg.shared.global [%0], [%1], 16;" :: "r"(saddr), "l"(gp));
    }
}

template <int EPI>
__global__ __launch_bounds__(256, 2)
void hgemm_kernel(const __half* __restrict__ A, const __half* __restrict__ A2,
                  int ksplit, int ldA,
                  const __half* __restrict__ W, int ldW,
                  void* __restrict__ Cv, int ldC, int K,
                  const float* __restrict__ gb,
                  const __half* __restrict__ oin,
                  const __half* __restrict__ qkvp) {
    extern __shared__ unsigned smem[];
    unsigned* AsB = smem;
    unsigned* WsB = smem + NSTG * SBUF_U;
    int tid = threadIdx.x;
    int wid = tid >> 5, lane = tid & 31;
    int warp_m = wid & 1, warp_n = wid >> 1;
    int m0 = blockIdx.y * 128, n0 = blockIdx.x * 128;
    const __half* Ag  = A  + (size_t)m0 * ldA;
    const __half* Ag2 = A2 + (size_t)m0 * ldA;
    const __half* Wg  = W  + (size_t)n0 * ldW;
    int qr = lane >> 2, qc = lane & 3;

    int mi = lane >> 3, rr = lane & 7;
    int lrow_a = warp_m * 64 + (mi & 1) * 8 + rr;
    int lrow_b = warp_n * 32 + (mi & 1) * 8 + rr;
    int lcol   = (mi >> 1) * 4;

    unsigned aBase = (unsigned)__cvta_generic_to_shared(AsB);
    unsigned bBase = (unsigned)__cvta_generic_to_shared(WsB);

    float acc[4][4][4];
    #pragma unroll
    for (int mt = 0; mt < 4; mt++)
        #pragma unroll
        for (int nt = 0; nt < 4; nt++)
            #pragma unroll
            for (int i = 0; i < 4; i++) acc[mt][nt][i] = 0.0f;

    int KT = K / 64;

    #pragma unroll
    for (int p = 0; p < 2; p++) {
        int k0 = p * 64;
        const __half* a0 = (k0 < ksplit) ? Ag : Ag2;
        int ak0 = (k0 < ksplit) ? k0 : k0 - ksplit;
        tile_load_h(AsB + p * SBUF_U, a0, ldA, ak0, tid);
        tile_load_h(WsB + p * SBUF_U, Wg, ldW, k0, tid);
        asm volatile("cp.async.commit_group;" ::: "memory");
    }

    for (int kt = 0; kt < KT; kt++) {
        int cur = kt % NSTG;
        if (kt + 1 < KT) asm volatile("cp.async.wait_group 1;" ::: "memory");
        else             asm volatile("cp.async.wait_group 0;" ::: "memory");
        __syncthreads();
        if (kt + 2 < KT) {
            int k0 = (kt + 2) * 64;
            int slot = (kt + 2) % NSTG;
            const __half* a0 = (k0 < ksplit) ? Ag : Ag2;
            int ak0 = (k0 < ksplit) ? k0 : k0 - ksplit;
            tile_load_h(AsB + slot * SBUF_U, a0, ldA, ak0, tid);
            tile_load_h(WsB + slot * SBUF_U, Wg, ldW, k0, tid);
            asm volatile("cp.async.commit_group;" ::: "memory");
        }
        unsigned aT = aBase + (cur * SBUF_U + lrow_a * UPITCH + lcol) * 4;
        unsigned bT = bBase + (cur * SBUF_U + lrow_b * UPITCH + lcol) * 4;
        #pragma unroll
        for (int ks = 0; ks < 4; ks++) {
            unsigned af[4][4], bf[4][2];
            #pragma unroll
            for (int mt = 0; mt < 4; mt++)
                ldsm_x4(af[mt], aT + (mt * 16 * UPITCH + ks * 8) * 4);
            #pragma unroll
            for (int ntp = 0; ntp < 2; ntp++) {
                unsigned t[4];
                ldsm_x4(t, bT + (ntp * 16 * UPITCH + ks * 8) * 4);
                bf[2 * ntp][0] = t[0]; bf[2 * ntp + 1][0] = t[1];
                bf[2 * ntp][1] = t[2]; bf[2 * ntp + 1][1] = t[3];
            }
            #pragma unroll
            for (int mt = 0; mt < 4; mt++)
                #pragma unroll
                for (int nt = 0; nt < 4; nt++)
                    mma_f16(acc[mt][nt], af[mt], bf[nt]);
        }
    }

    #pragma unroll
    for (int mt = 0; mt < 4; mt++)
        #pragma unroll
        for (int nt = 0; nt < 4; nt++) {
            int row = m0 + warp_m * 64 + mt * 16 + qr;
            int col = n0 + warp_n * 32 + nt * 8 + qc * 2;
            float2 r0 = make_float2(acc[mt][nt][0], acc[mt][nt][1]);
            float2 r1 = make_float2(acc[mt][nt][2], acc[mt][nt][3]);
            if (EPI == 0) {
                __half* Ch = (__half*)Cv;
                *(__half2*)(Ch + (size_t)row * ldC + col)       = __floats2half2_rn(r0.x, r0.y);
                *(__half2*)(Ch + (size_t)(row + 8) * ldC + col) = __floats2half2_rn(r1.x, r1.y);
            } else if (EPI == 1) {
                float* Cf = (float*)Cv;
                float* p0 = Cf + (size_t)row * ldC + col;
                float* p1 = Cf + (size_t)(row + 8) * ldC + col;
                float2 o0 = *(float2*)p0, o1 = *(float2*)p1;
                *(float2*)p0 = make_float2(r0.x + o0.x, r0.y + o0.y);
                *(float2*)p1 = make_float2(r1.x + o1.x, r1.y + o1.y);
            } else if (EPI == 2) {
                __half* Ch = (__half*)Cv;
                float2 gbv = *(const float2*)(gb + col);
                float2 o0 = __half22float2(*(const __half2*)(oin + (size_t)row * HID + col));
                float2 o1 = __half22float2(*(const __half2*)(oin + (size_t)(row + 8) * HID + col));
                float2 v0 = __half22float2(*(const __half2*)(qkvp + (size_t)row * 3072 + 2048 + col));
                float2 v1 = __half22float2(*(const __half2*)(qkvp + (size_t)(row + 8) * 3072 + 2048 + col));
                float g00 = sigmoidf_(r0.x + gbv.x), g01 = sigmoidf_(r0.y + gbv.y);
                float g10 = sigmoidf_(r1.x + gbv.x), g11 = sigmoidf_(r1.y + gbv.y);
                *(__half2*)(Ch + (size_t)row * ldC + col) =
                    __floats2half2_rn(g00 * o0.x + (1.0f - g00) * v0.x,
                                      g01 * o0.y + (1.0f - g01) * v0.y);
                *(__half2*)(Ch + (size_t)(row + 8) * ldC + col) =
                    __floats2half2_rn(g10 * o1.x + (1.0f - g10) * v1.x,
                                      g11 * o1.y + (1.0f - g11) * v1.y);
            } else {  // EPI == 3
                __half* Ch = (__half*)Cv;
                int ocol = col >> 1;
                Ch[(size_t)row * ldC + ocol]       = __float2half_rn(siluf_(r0.x) * r0.y);
                Ch[(size_t)(row + 8) * ldC + ocol] = __float2half_rn(siluf_(r1.x) * r1.y);
            }
        }
}

// ---------------- depthwise conv (KS=4) + bias + silu ----------------------
__global__ void conv_silu_kernel(const __half* __restrict__ h, const float* __restrict__ cw,
                                 const float* __restrict__ cb, __half* __restrict__ o) {
    __shared__ float tapT[KS][HID];
    int tid = threadIdx.x;
    int row = blockIdx.x;
    int t = row & (TT - 1);
    int b = row >> 11;
    #pragma unroll
    for (int i = 0; i < 4; i++) {
        int ch = tid + i * 256;
        float4 w = *(const float4*)(cw + ch * KS);
        tapT[0][ch] = w.x; tapT[1][ch] = w.y; tapT[2][ch] = w.z; tapT[3][ch] = w.w;
    }
    __syncthreads();
    int c = tid * 4;
    float4 acc = *(const float4*)(cb + c);
    #pragma unroll
    for (int j = 0; j < KS; j++) {
        int tt = t + j - (KS - 1);
        if (tt >= 0) {
            uint2 hv4 = *(const uint2*)(h + ((size_t)(b * TT + tt)) * HID + c);
            float2 h01 = __half22float2(*(__half2*)&hv4.x);
            float2 h23 = __half22float2(*(__half2*)&hv4.y);
            float4 tp = *(const float4*)(&tapT[j][c]);
            acc.x += h01.x * tp.x; acc.y += h01.y * tp.y;
            acc.z += h23.x * tp.z; acc.w += h23.y * tp.w;
        }
    }
    uint2 r = f4_to_h4(make_float4(siluf_(acc.x), siluf_(acc.y),
                                   siluf_(acc.z), siluf_(acc.w)));
    *(uint2*)(o + (size_t)row * HID + c) = r;
}

// ---------------- scan pass A (elu+1 on k inline), half rks/rkv ------------
__global__ void scan_chunk_kernel(const __half* __restrict__ qkv, const float* __restrict__ dp,
                                  __half* __restrict__ rks, __half* __restrict__ rkv,
                                  float* __restrict__ cks, float* __restrict__ ckv) {
    int c = blockIdx.x * blockDim.x + threadIdx.x;
    int j = blockIdx.y;
    int b = blockIdx.z;
    float d = sigmoidf_(dp[c >> 7]);
    float sks = 0.0f, skv = 0.0f;
    size_t base  = ((size_t)(b * TT + j * CLEN)) * 3072 + c;
    size_t obase = ((size_t)(b * TT + j * CLEN)) * HID + c;
    for (int i = 0; i < CLEN; i++) {
        float kk = elup1_(__half2float(qkv[base + 1024]));
        float vv = __half2float(qkv[base + 2048]);
        sks = d * sks + kk;
        skv = d * skv + kk * vv;
        rks[obase] = __float2half_rn(sks);
        rkv[obase] = __float2half_rn(skv);
        base += 3072; obase += HID;
    }
    cks[(b * NCHUNK + j) * HID + c] = sks;
    ckv[(b * NCHUNK + j) * HID + c] = skv;
}

// ---------------- scan pass B ---------------------------------------------
__global__ void scan_carry_kernel(const float* __restrict__ dp,
                                  const float* __restrict__ cks, const float* __restrict__ ckv,
                                  float* __restrict__ pks, float* __restrict__ pkv) {
    int c = blockIdx.x * blockDim.x + threadIdx.x;
    int b = blockIdx.y;
    float d = sigmoidf_(dp[c >> 7]);
    float dC = expf((float)CLEN * logf(d));
    float sks = 0.0f, skv = 0.0f;
    for (int j = 0; j < NCHUNK; j++) {
        int idx = (b * NCHUNK + j) * HID + c;
        pks[idx] = sks;
        pkv[idx] = skv;
        sks = dC * sks + cks[idx];
        skv = dC * skv + ckv[idx];
    }
}

// ---------------- attn_o (fused elu/carry/den), half in/out ----------------
__global__ void attn_o_kernel(const __half* __restrict__ qkv, const float* __restrict__ dp,
                              const __half* __restrict__ rks, const __half* __restrict__ rkv,
                              const float* __restrict__ pks, const float* __restrict__ pkv,
                              __half* __restrict__ o) {
    int gw = (blockIdx.x * blockDim.x + threadIdx.x) >> 5;
    int lane = threadIdx.x & 31;
    int row = gw >> 3;
    int hh = gw & 7;
    int b = row >> 11;
    int t = row & (TT - 1);
    int i = t & (CLEN - 1);
    int j = t >> 7;
    float d  = sigmoidf_(dp[hh]);
    float pw = expf((float)(i + 1) * logf(d));
    size_t qbase = (size_t)row * 3072 + hh * HD;
    size_t rbase = (size_t)row * HID  + hh * HD;
    size_t pbase = (size_t)(b * NCHUNK + j) * HID + hh * HD;
    float qv[4], kvv[4], s = 0.0f;
    #pragma unroll
    for (int u = 0; u < 4; u++) {
        int dpos = lane + u * 32;
        qv[u] = elup1_(__half2float(qkv[qbase + dpos]));
        float ks = __half2float(rks[rbase + dpos]) + pks[pbase + dpos] * pw;
        kvv[u]  = __half2float(rkv[rbase + dpos]) + pkv[pbase + dpos] * pw;
        s += qv[u] * ks;
    }
    #pragma unroll
    for (int k = 16; k; k >>= 1) s += __shfl_xor_sync(0xFFFFFFFFu, s, k);
    float inv = 1.0f / fmaxf(s, 1e-6f);
    #pragma unroll
    for (int u = 0; u < 4; u++) {
        int dpos = lane + u * 32;
        o[rbase + dpos] = __float2half_rn(qv[u] * kvv[u] * inv);
    }
}

// ---------------- gmix residual + rmsnorm2 ---------------------------------
__global__ void gmix_norm_kernel(const float* __restrict__ x, const __half* __restrict__ glin,
                                 const __half* __restrict__ local, const __half* __restrict__ attn,
                                 const float* __restrict__ w2n,
                                 float* __restrict__ x1out, __half* __restrict__ h2) {
    int row = blockIdx.x;
    size_t base = (size_t)row * HID;
    int tid = threadIdx.x;
    float4 xv = ((const float4*)(x + base))[tid];
    uint2 gu = ((const uint2*)(glin + base))[tid];
    uint2 lu = ((const uint2*)(local + base))[tid];
    uint2 au = ((const uint2*)(attn + base))[tid];
    float2 g01 = __half22float2(*(__half2*)&gu.x), g23 = __half22float2(*(__half2*)&gu.y);
    float2 l01 = __half22float2(*(__half2*)&lu.x), l23 = __half22float2(*(__half2*)&lu.y);
    float2 a01 = __half22float2(*(__half2*)&au.x), a23 = __half22float2(*(__half2*)&au.y);
    float s0 = sigmoidf_(g01.x), s1 = sigmoidf_(g01.y);
    float s2 = sigmoidf_(g23.x), s3 = sigmoidf_(g23.y);
    float4 x1v = make_float4(xv.x + s0 * l01.x + (1.0f - s0) * a01.x,
                             xv.y + s1 * l01.y + (1.0f - s1) * a01.y,
                             xv.z + s2 * l23.x + (1.0f - s2) * a23.x,
                             xv.w + s3 * l23.y + (1.0f - s3) * a23.y);
    ((float4*)(x1out + base))[tid] = x1v;
    float ss = x1v.x * x1v.x + x1v.y * x1v.y + x1v.z * x1v.z + x1v.w * x1v.w;
    __shared__ float sred[8];
    int lane = tid & 31, wid = tid >> 5;
    #pragma unroll
    for (int k = 16; k; k >>= 1) ss += __shfl_xor_sync(0xFFFFFFFFu, ss, k);
    if (lane == 0) sred[wid] = ss;
    __syncthreads();
    if (wid == 0) {
        float t = (lane < 8) ? sred[lane] : 0.0f;
        #pragma unroll
        for (int k = 4; k; k >>= 1) t += __shfl_xor_sync(0xFFFFFFFFu, t, k);
        if (lane == 0) sred[0] = t;
    }
    __syncthreads();
    float scale = rsqrtf(sred[0] * (1.0f / (float)HID) + 1e-6f);
    float4 wv = ((const float4*)w2n)[tid];
    uint2 r = f4_to_h4(make_float4(x1v.x * scale * wv.x, x1v.y * scale * wv.y,
                                   x1v.z * scale * wv.z, x1v.w * scale * wv.w));
    ((uint2*)(h2 + base))[tid] = r;
}

// ---------------- host side ------------------------------------------------
#define BIGK 0x40000000

static inline void run_gemm_s(cudaStream_t st,
                              const __half* A, const __half* A2, int ksplit, int ldA,
                              const __half* W, int ldW,
                              void* C, int ldC, int M, int N, int K,
                              int epi,
                              const float* gb = nullptr, const __half* oin = nullptr,
                              const __half* qkvp = nullptr) {
    dim3 grid(N / 128, M / 128);
    if (epi == 3)
        hgemm_kernel<3><<<grid, 256, TGEMM_SMEM, st>>>(A, A2, ksplit, ldA, W, ldW, C, ldC, K, nullptr, nullptr, nullptr);
    else if (epi == 2)
        hgemm_kernel<2><<<grid, 256, TGEMM_SMEM, st>>>(A, A2, ksplit, ldA, W, ldW, C, ldC, K, gb, oin, qkvp);
    else if (epi == 1)
        hgemm_kernel<1><<<grid, 256, TGEMM_SMEM, st>>>(A, A2, ksplit, ldA, W, ldW, C, ldC, K, nullptr, nullptr, nullptr);
    else
        hgemm_kernel<0><<<grid, 256, TGEMM_SMEM, st>>>(A, A2, ksplit, ldA, W, ldW, C, ldC, K, nullptr, nullptr, nullptr);
}

extern "C" void kernel_launch(void* const* d_in, const int* in_sizes, int n_in,
                              void* d_out, int out_size) {
    const float* x           = (const float*)d_in[0];
    const float* qkv_w       = (const float*)d_in[1];
    const float* out_proj_w  = (const float*)d_in[2];
    const float* out_gate_w  = (const float*)d_in[3];
    const float* out_gate_b  = (const float*)d_in[4];
    const float* decay_param = (const float*)d_in[5];
    const float* conv_w      = (const float*)d_in[6];
    const float* conv_b      = (const float*)d_in[7];
    const float* pw_w        = (const float*)d_in[8];
    const float* gate_w      = (const float*)d_in[9];
    const float* w1          = (const float*)d_in[10];
    const float* w2          = (const float*)d_in[11];
    const float* w3          = (const float*)d_in[12];
    const float* norm1_w     = (const float*)d_in[13];
    const float* norm2_w     = (const float*)d_in[14];
    float* out = (float*)d_out;

    static int init_done = 0;
    static cudaStream_t s2;
    static cudaEvent_t evFork, evJoin;
    if (!init_done) {
        cudaFuncSetAttribute(hgemm_kernel<0>,
                             cudaFuncAttributeMaxDynamicSharedMemorySize, (int)TGEMM_SMEM);
        cudaFuncSetAttribute(hgemm_kernel<1>,
                             cudaFuncAttributeMaxDynamicSharedMemorySize, (int)TGEMM_SMEM);
        cudaFuncSetAttribute(hgemm_kernel<2>,
                             cudaFuncAttributeMaxDynamicSharedMemorySize, (int)TGEMM_SMEM);
        cudaFuncSetAttribute(hgemm_kernel<3>,
                             cudaFuncAttributeMaxDynamicSharedMemorySize, (int)TGEMM_SMEM);
        cudaStreamCreateWithFlags(&s2, cudaStreamNonBlocking);
        cudaEventCreateWithFlags(&evFork, cudaEventDisableTiming);
        cudaEventCreateWithFlags(&evJoin, cudaEventDisableTiming);
        init_done = 1;
    }

    float* S = nullptr;
    cudaGetSymbolAddress((void**)&S, g_scratch);

    __half* g_h    = (__half*)(S + OFF_H);
    __half* g_qkv  = (__half*)(S + OFF_QKV);
    __half* g_conv = (__half*)(S + OFF_CONV);
    __half* g_loc  = (__half*)(S + OFF_LOCAL);
    __half* g_o    = (__half*)(S + OFF_O);
    __half* g_tmp  = (__half*)(S + OFF_TMP);
    __half* g_o2   = (__half*)(S + OFF_O2);
    __half* g_attn = (__half*)(S + OFF_ATTN);
    __half* g_h2   = (__half*)(S + OFF_H2);
    __half* g_ffa  = (__half*)(S + OFF_FFA);
    __half* g_rks  = (__half*)(S + OFF_RKS);
    __half* g_rkv  = (__half*)(S + OFF_RKV);
    float*  g_cks  = S + OFF_CKS;
    float*  g_ckv  = S + OFF_CKV;
    float*  g_pks  = S + OFF_PKS;
    float*  g_pkv  = S + OFF_PKV;
    __half* c_qkvw = (__half*)(S + OFF_WQKV);
    __half* c_opw  = (__half*)(S + OFF_WOP);
    __half* c_ogw  = (__half*)(S + OFF_WOG);
    __half* c_pww  = (__half*)(S + OFF_WPW);
    __half* c_gtw  = (__half*)(S + OFF_WGT);
    __half* c_w3   = (__half*)(S + OFF_WW3);
    __half* c_w12  = (__half*)(S + OFF_W12);

    cudaStream_t m = 0;   // default (captured) stream

    // 0. one fused weight-prep launch
    weight_prep_kernel<<<(C7 + 255) / 256, 256, 0, m>>>(
        (const float4*)qkv_w, (const float4*)out_proj_w, (const float4*)out_gate_w,
        (const float4*)pw_w, (const float4*)gate_w, (const float4*)w3,
        (const float4*)w1, (const float4*)w2,
        (uint2*)c_qkvw, (uint2*)c_opw, (uint2*)c_ogw, (uint2*)c_pww,
        (uint2*)c_gtw, (uint2*)c_w3, (uint2*)c_w12);

    // 1. h = rmsnorm(x, norm1_w)
    rmsnorm_kernel<<<MROWS, 256, 0, m>>>(x, norm1_w, g_h);

    // ---- fork: conv branch on s2 (depends on g_h + c_pww, both done) ----
    cudaEventRecord(evFork, m);
    cudaStreamWaitEvent(s2, evFork, 0);
    conv_silu_kernel<<<MROWS, 256, 0, s2>>>(g_h, conv_w, conv_b, g_conv);
    run_gemm_s(s2, g_conv, g_conv, BIGK, HID, c_pww, HID, g_loc, HID, MROWS, HID, HID, 0);
    cudaEventRecord(evJoin, s2);

    // ---- main chain ----
    // 2. qkv = h @ qkv_w^T
    run_gemm_s(m, g_h, g_h, BIGK, HID, c_qkvw, HID, g_qkv, 3 * HID, MROWS, 3 * HID, HID, 0);

    // 3. decayed scans
    {
        dim3 gA(HID / 256, NCHUNK, BB);
        scan_chunk_kernel<<<gA, 256, 0, m>>>(g_qkv, decay_param, g_rks, g_rkv, g_cks, g_ckv);
        dim3 gB(HID / 256, BB);
        scan_carry_kernel<<<gB, 256, 0, m>>>(decay_param, g_cks, g_ckv, g_pks, g_pkv);
    }

    // 4. o
    attn_o_kernel<<<MROWS * NH * 32 / 256, 256, 0, m>>>(g_qkv, decay_param,
                                                        g_rks, g_rkv, g_pks, g_pkv, g_o);

    // 5. out gate GEMM + fused mix epilogue -> o2
    run_gemm_s(m, g_o, g_o, BIGK, HID, c_ogw, HID, g_o2, HID, MROWS, HID, HID, 2,
               out_gate_b, g_o, g_qkv);

    // 6. attn = o2 @ out_proj^T
    run_gemm_s(m, g_o2, g_o2, BIGK, HID, c_opw, HID, g_attn, HID, MROWS, HID, HID, 0);

    // ---- join: gate GEMM needs g_loc from s2 ----
    cudaStreamWaitEvent(m, evJoin, 0);

    // 7. gmix: dual-A GEMM over [local|attn] (K=2048), then residual+norm2
    run_gemm_s(m, g_loc, g_attn, HID, HID, c_gtw, 2 * HID, g_tmp, HID, MROWS, HID, 2 * HID, 0);
    gmix_norm_kernel<<<MROWS, 256, 0, m>>>(x, g_tmp, g_loc, g_attn, norm2_w, out, g_h2);

    // 8. FFN: w1|w2 interleaved GEMM + swiglu epilogue -> ffa; w3 += onto out
    run_gemm_s(m, g_h2, g_h2, BIGK, HID, c_w12, HID, g_ffa, INTER, MROWS, 2 * INTER, HID, 3);
    run_gemm_s(m, g_ffa, g_ffa, BIGK, INTER, c_w3, INTER, out, HID, MROWS, HID, INTER, 1);
}